// round 13
// baseline (speedup 1.0000x reference)
#include <cuda_runtime.h>
#include <cuda_fp16.h>
#include <math.h>

#define NN    50000
#define NE    800000
#define INF_  32
#define H     64
#define HV    16      // H/4 (float4 lanes per row)
#define EDIM  4
#define NL    3
#define NG    512
#define NOUT  2
#define NPAD  50048   // 782 * 64
#define BN_EPS 1e-5f
#define PN_EPS 1e-5f
#define EPB   128     // edges per block in edge_kernel (8 per 16-thread group)
#define ZPAD  68      // padded row stride (floats) for conflict-free mma frags

// ---------------- persistent device scratch (zero-initialized at load) -----
__device__ float d_h[NPAD * H];
__device__ __align__(16) __half d_h16[NPAD * H];   // fp16 shadow for gathers
__device__ float d_agg[NPAD * H];
__device__ float d_gsum[NG * H];
__device__ float d_gss[NG];
__device__ float d_gcnt[NG];
__device__ float d_mean[NG * H];
__device__ float d_invd[NG];
__device__ float d_pool[NG * H];

// 16-byte vector reduction to global (sm_90+)
__device__ __forceinline__ void red_add4(float4* a, float4 v) {
    asm volatile("red.global.add.v4.f32 [%0], {%1,%2,%3,%4};"
                 :: "l"(a), "f"(v.x), "f"(v.y), "f"(v.z), "f"(v.w) : "memory");
}
__device__ __forceinline__ void red_add2(float2* a, float v0, float v1) {
    asm volatile("red.global.add.v2.f32 [%0], {%1,%2};"
                 :: "l"(a), "f"(v0), "f"(v1) : "memory");
}

__device__ __forceinline__ float4 f4zero() { return make_float4(0.f, 0.f, 0.f, 0.f); }

__device__ __forceinline__ void f4fma(float4& acc, float s, const float4 w) {
    acc.x = fmaf(s, w.x, acc.x);
    acc.y = fmaf(s, w.y, acc.y);
    acc.z = fmaf(s, w.z, acc.z);
    acc.w = fmaf(s, w.w, acc.w);
}

__device__ __forceinline__ float4 f4relu_add(float4 a, float4 b) {
    return make_float4(fmaxf(a.x + b.x, 0.f), fmaxf(a.y + b.y, 0.f),
                       fmaxf(a.z + b.z, 0.f), fmaxf(a.w + b.w, 0.f));
}

__device__ __forceinline__ uint2 f4_to_h4(float4 v) {
    __half2 lo = __floats2half2_rn(v.x, v.y);
    __half2 hi = __floats2half2_rn(v.z, v.w);
    uint2 r;
    r.x = *reinterpret_cast<unsigned*>(&lo);
    r.y = *reinterpret_cast<unsigned*>(&hi);
    return r;
}

__device__ __forceinline__ float4 h4_to_f4(uint2 u) {
    __half2 lo = *reinterpret_cast<__half2*>(&u.x);
    __half2 hi = *reinterpret_cast<__half2*>(&u.y);
    float2 a = __half22float2(lo);
    float2 b = __half22float2(hi);
    return make_float4(a.x, a.y, b.x, b.y);
}

__device__ __forceinline__ float tf32r(float x) {
    unsigned u;
    asm("cvt.rna.tf32.f32 %0, %1;" : "=r"(u) : "f"(x));
    return __uint_as_float(u);
}
__device__ __forceinline__ float4 tf32r4(float4 v) {
    return make_float4(tf32r(v.x), tf32r(v.y), tf32r(v.z), tf32r(v.w));
}

__device__ __forceinline__ void mma16n8k8(float c[4], unsigned a0, unsigned a1,
                                          unsigned a2, unsigned a3,
                                          unsigned b0, unsigned b1) {
    asm volatile(
        "mma.sync.aligned.m16n8k8.row.col.f32.tf32.tf32.f32 "
        "{%0,%1,%2,%3}, {%4,%5,%6,%7}, {%8,%9}, {%0,%1,%2,%3};"
        : "+f"(c[0]), "+f"(c[1]), "+f"(c[2]), "+f"(c[3])
        : "r"(a0), "r"(a1), "r"(a2), "r"(a3), "r"(b0), "r"(b1));
}

// ---------------- counts: batch is sorted -> binary search per graph -------
__global__ void count_kernel(const int* __restrict__ batch) {
    int g = blockIdx.x * blockDim.x + threadIdx.x;
    if (g >= NG) return;
    int lo = 0, hi = NN;
    while (lo < hi) { int m = (lo + hi) >> 1; if (batch[m] < g) lo = m + 1; else hi = m; }
    int s = lo;
    lo = 0; hi = NN;
    while (lo < hi) { int m = (lo + hi) >> 1; if (batch[m] < g + 1) lo = m + 1; else hi = m; }
    d_gcnt[g] = fmaxf((float)(lo - s), 1.0f);
}

// ---------------- input linear: h = x @ W_in + b ; zeroes d_agg; h16 -------
__global__ void __launch_bounds__(256) lin_in_kernel(const float* __restrict__ x,
                                                     const float* __restrict__ W,
                                                     const float* __restrict__ b) {
    __shared__ __align__(16) float4 Ws[INF_ * HV];
    __shared__ __align__(16) float4 bs[HV];
    int t = threadIdx.x;
    for (int j = t; j < INF_ * HV; j += 256) Ws[j] = ((const float4*)W)[j];
    if (t < HV) bs[t] = ((const float4*)b)[t];
    __syncthreads();

    int lane = t & 15, rloc = t >> 4;
    int row = blockIdx.x * 16 + rloc;

    ((float4*)d_agg)[row * HV + lane] = f4zero();

    if (row < NN) {
        float4 acc = bs[lane];
        const float* xr = x + row * INF_;
        #pragma unroll
        for (int k = 0; k < INF_; k++) {
            float xv = __ldg(xr + k);
            f4fma(acc, xv, Ws[k * HV + lane]);
        }
        ((float4*)d_h)[row * HV + lane] = acc;
        ((uint2*)d_h16)[row * HV + lane] = f4_to_h4(acc);
    }
}

// ---------------- edge kernel: agg[dst] += relu(h16[src] + ea @ We + be) ---
__global__ void __launch_bounds__(256) edge_kernel(const int* __restrict__ ei,
                                                   const float* __restrict__ eattr,
                                                   const float* __restrict__ eW,
                                                   const float* __restrict__ eb) {
    __shared__ __align__(16) float4 Ws[EDIM * HV];
    __shared__ __align__(16) float4 bs[HV];
    int t = threadIdx.x;
    if (t < EDIM * HV) Ws[t] = ((const float4*)eW)[t];
    if (t < HV) bs[t] = ((const float4*)eb)[t];
    __syncthreads();

    int e0   = blockIdx.x * EPB + (t >> 4) * 8;
    int lane = t & 15;

    int4 sa = __ldg((const int4*)(ei) + (e0 >> 2));
    int4 sb = __ldg((const int4*)(ei) + (e0 >> 2) + 1);
    int4 da = __ldg((const int4*)(ei + NE) + (e0 >> 2));
    int4 db = __ldg((const int4*)(ei + NE) + (e0 >> 2) + 1);
    int src[8] = {sa.x, sa.y, sa.z, sa.w, sb.x, sb.y, sb.z, sb.w};
    int dst[8] = {da.x, da.y, da.z, da.w, db.x, db.y, db.z, db.w};

    uint2 hr[8];
    #pragma unroll
    for (int j = 0; j < 8; j++)
        hr[j] = __ldg((const uint2*)d_h16 + src[j] * HV + lane);

    float4 a[8];
    #pragma unroll
    for (int j = 0; j < 8; j++) a[j] = __ldg((const float4*)eattr + e0 + j);

    float4 w0 = Ws[0 * HV + lane], w1 = Ws[1 * HV + lane];
    float4 w2 = Ws[2 * HV + lane], w3 = Ws[3 * HV + lane];
    float4 bv = bs[lane];

    #pragma unroll
    for (int j = 0; j < 8; j++) {
        float4 v = bv;
        f4fma(v, a[j].x, w0);
        f4fma(v, a[j].y, w1);
        f4fma(v, a[j].z, w2);
        f4fma(v, a[j].w, w3);
        float4 m = f4relu_add(v, h4_to_f4(hr[j]));
        red_add4((float4*)d_agg + dst[j] * HV + lane, m);
    }
}

// ---------------- fused node MLP via tf32 mma.sync -------------------------
// z = (1+eps)*h + agg ; t = relu(BN1(z@W1+b1)) [smem] ; h' = relu(BN2(t@W2+b2))
// A (zs) row-major [64][ZPAD], B (WsT) n-major [64][ZPAD]. 64-row tile/block.
// Warp w: rows m0=(w&3)*16, cols n0=(w>>2)*32 (4 n-tiles of 8).
__global__ void __launch_bounds__(256) mlp_fused_kernel(
    const float* __restrict__ W1, const float* __restrict__ b1,
    const float* __restrict__ g1, const float* __restrict__ be1,
    const float* __restrict__ rm1, const float* __restrict__ rv1,
    const float* __restrict__ W2, const float* __restrict__ b2,
    const float* __restrict__ g2, const float* __restrict__ be2,
    const float* __restrict__ rm2, const float* __restrict__ rv2,
    const float* __restrict__ epsp, const int* __restrict__ batch, int do_pn)
{
    __shared__ __align__(16) float zs[64 * ZPAD];
    __shared__ __align__(16) float WsT[64 * ZPAD];
    __shared__ __align__(16) float s1s[H], s2s[H], bias1[H], bias2[H];

    int t = threadIdx.x;
    int lane = t & 31, w = t >> 5;
    int tig = lane & 3, g = lane >> 2;
    int m0 = (w & 3) * 16, n0 = (w >> 2) * 32;
    int R0 = blockIdx.x * 64;
    float epv = 1.0f + __ldg(epsp);

    // --- phase (a): batch global loads; t<64 computes BN folds -------------
    float4 wv[4], hvv[4], avv[4];
    #pragma unroll
    for (int s = 0; s < 4; s++) {
        wv[s]  = __ldg((const float4*)W1 + t + 256 * s);
        hvv[s] = __ldg((const float4*)d_h + R0 * HV + t + 256 * s);
        avv[s] = __ldg((const float4*)d_agg + R0 * HV + t + 256 * s);
    }
    if (t < H) {
        float s1 = __ldg(g1 + t) * rsqrtf(__ldg(rv1 + t) + BN_EPS);
        s1s[t] = s1;
        bias1[t] = fmaf(__ldg(b1 + t) - __ldg(rm1 + t), s1, __ldg(be1 + t));
        float s2 = __ldg(g2 + t) * rsqrtf(__ldg(rv2 + t) + BN_EPS);
        s2s[t] = s2;
        bias2[t] = fmaf(__ldg(b2 + t) - __ldg(rm2 + t), s2, __ldg(be2 + t));
    }
    __syncthreads();

    // --- phase (b): stage scaled W1 (transposed, tf32) and z (tf32) --------
    #pragma unroll
    for (int s = 0; s < 4; s++) {
        int idx = t + 256 * s;                 // float4 index in [0,1024)
        int k  = idx >> 4;                     // W row (k), z row
        int n4 = (idx & 15) * 4;               // W col base / z k base
        float4 sc = *(const float4*)&s1s[n4];
        float4 ww = wv[s];
        WsT[(n4 + 0) * ZPAD + k] = tf32r(ww.x * sc.x);
        WsT[(n4 + 1) * ZPAD + k] = tf32r(ww.y * sc.y);
        WsT[(n4 + 2) * ZPAD + k] = tf32r(ww.z * sc.z);
        WsT[(n4 + 3) * ZPAD + k] = tf32r(ww.w * sc.w);
        float4 hv = hvv[s], av = avv[s];
        float4 z = make_float4(fmaf(epv, hv.x, av.x), fmaf(epv, hv.y, av.y),
                               fmaf(epv, hv.z, av.z), fmaf(epv, hv.w, av.w));
        *(float4*)&zs[k * ZPAD + n4] = tf32r4(z);
        if (do_pn) ((float4*)d_agg)[R0 * HV + idx] = f4zero();
    }
    __syncthreads();

    // --- GEMM1 -------------------------------------------------------------
    float c[4][4];
    #pragma unroll
    for (int nt = 0; nt < 4; nt++)
        c[nt][0] = c[nt][1] = c[nt][2] = c[nt][3] = 0.f;
    #pragma unroll
    for (int kk = 0; kk < 8; kk++) {
        int k0 = kk * 8;
        unsigned a0 = __float_as_uint(zs[(m0 + g) * ZPAD + k0 + tig]);
        unsigned a1 = __float_as_uint(zs[(m0 + g + 8) * ZPAD + k0 + tig]);
        unsigned a2 = __float_as_uint(zs[(m0 + g) * ZPAD + k0 + tig + 4]);
        unsigned a3 = __float_as_uint(zs[(m0 + g + 8) * ZPAD + k0 + tig + 4]);
        #pragma unroll
        for (int nt = 0; nt < 4; nt++) {
            unsigned b0 = __float_as_uint(WsT[(n0 + nt * 8 + g) * ZPAD + k0 + tig]);
            unsigned b1 = __float_as_uint(WsT[(n0 + nt * 8 + g) * ZPAD + k0 + tig + 4]);
            mma16n8k8(c[nt], a0, a1, a2, a3, b0, b1);
        }
    }

    // prefetch W2 while waiting
    #pragma unroll
    for (int s = 0; s < 4; s++) wv[s] = __ldg((const float4*)W2 + t + 256 * s);

    __syncthreads();   // GEMM1 reads of zs/WsT complete

    // --- phase (d): stage t -> zs (relu+bias1, tf32) and scaled W2T --------
    #pragma unroll
    for (int nt = 0; nt < 4; nt++) {
        int col = n0 + nt * 8 + 2 * tig;
        float bA0 = bias1[col], bA1 = bias1[col + 1];
        float v0 = fmaxf(c[nt][0] + bA0, 0.f), v1 = fmaxf(c[nt][1] + bA1, 0.f);
        float v2 = fmaxf(c[nt][2] + bA0, 0.f), v3 = fmaxf(c[nt][3] + bA1, 0.f);
        float2* p0 = (float2*)&zs[(m0 + g) * ZPAD + col];
        float2* p1 = (float2*)&zs[(m0 + g + 8) * ZPAD + col];
        *p0 = make_float2(tf32r(v0), tf32r(v1));
        *p1 = make_float2(tf32r(v2), tf32r(v3));
    }
    #pragma unroll
    for (int s = 0; s < 4; s++) {
        int idx = t + 256 * s;
        int k  = idx >> 4;
        int n4 = (idx & 15) * 4;
        float4 sc = *(const float4*)&s2s[n4];
        float4 ww = wv[s];
        WsT[(n4 + 0) * ZPAD + k] = tf32r(ww.x * sc.x);
        WsT[(n4 + 1) * ZPAD + k] = tf32r(ww.y * sc.y);
        WsT[(n4 + 2) * ZPAD + k] = tf32r(ww.z * sc.z);
        WsT[(n4 + 3) * ZPAD + k] = tf32r(ww.w * sc.w);
    }
    __syncthreads();

    // --- GEMM2 -------------------------------------------------------------
    #pragma unroll
    for (int nt = 0; nt < 4; nt++)
        c[nt][0] = c[nt][1] = c[nt][2] = c[nt][3] = 0.f;
    #pragma unroll
    for (int kk = 0; kk < 8; kk++) {
        int k0 = kk * 8;
        unsigned a0 = __float_as_uint(zs[(m0 + g) * ZPAD + k0 + tig]);
        unsigned a1 = __float_as_uint(zs[(m0 + g + 8) * ZPAD + k0 + tig]);
        unsigned a2 = __float_as_uint(zs[(m0 + g) * ZPAD + k0 + tig + 4]);
        unsigned a3 = __float_as_uint(zs[(m0 + g + 8) * ZPAD + k0 + tig + 4]);
        #pragma unroll
        for (int nt = 0; nt < 4; nt++) {
            unsigned b0 = __float_as_uint(WsT[(n0 + nt * 8 + g) * ZPAD + k0 + tig]);
            unsigned b1 = __float_as_uint(WsT[(n0 + nt * 8 + g) * ZPAD + k0 + tig + 4]);
            mma16n8k8(c[nt], a0, a1, a2, a3, b0, b1);
        }
    }

    // --- epilogue: BN2+ReLU, store h, PN stats / pool ----------------------
    int rowA = R0 + m0 + g;
    int rowB = rowA + 8;
    bool okA = rowA < NN, okB = rowB < NN;
    int ggA = okA ? __ldg(batch + rowA) : 0;
    int ggB = okB ? __ldg(batch + rowB) : 0;
    float sqA = 0.f, sqB = 0.f;

    #pragma unroll
    for (int nt = 0; nt < 4; nt++) {
        int col = n0 + nt * 8 + 2 * tig;
        float bA0 = bias2[col], bA1 = bias2[col + 1];
        float v0 = fmaxf(c[nt][0] + bA0, 0.f), v1 = fmaxf(c[nt][1] + bA1, 0.f);
        float v2 = fmaxf(c[nt][2] + bA0, 0.f), v3 = fmaxf(c[nt][3] + bA1, 0.f);
        if (okA) *(float2*)&d_h[rowA * H + col] = make_float2(v0, v1);
        if (okB) *(float2*)&d_h[rowB * H + col] = make_float2(v2, v3);
        if (do_pn) {
            if (okA) red_add2((float2*)&d_gsum[ggA * H + col], v0, v1);
            if (okB) red_add2((float2*)&d_gsum[ggB * H + col], v2, v3);
            sqA = fmaf(v0, v0, fmaf(v1, v1, sqA));
            sqB = fmaf(v2, v2, fmaf(v3, v3, sqB));
        } else {
            if (okA) red_add2((float2*)&d_pool[ggA * H + col], v0, v1);
            if (okB) red_add2((float2*)&d_pool[ggB * H + col], v2, v3);
        }
    }
    if (do_pn) {
        sqA += __shfl_xor_sync(0xffffffffu, sqA, 1);
        sqA += __shfl_xor_sync(0xffffffffu, sqA, 2);
        sqB += __shfl_xor_sync(0xffffffffu, sqB, 1);
        sqB += __shfl_xor_sync(0xffffffffu, sqB, 2);
        if (tig == 0) {
            if (okA) atomicAdd(&d_gss[ggA], sqA);
            if (okB) atomicAdd(&d_gss[ggB], sqB);
        }
    }
}

// ---------------- PairNorm per-graph mean & inverse denom; self-re-zeros ---
__global__ void meaninv_kernel() {
    int g = blockIdx.x, c = threadIdx.x;     // 64 threads
    float cnt = d_gcnt[g];
    float s = d_gsum[g * H + c];
    d_gsum[g * H + c] = 0.f;
    float mean = s / cnt;
    d_mean[g * H + c] = mean;
    float part = mean * s;
    #pragma unroll
    for (int o = 16; o; o >>= 1) part += __shfl_down_sync(0xffffffffu, part, o);
    __shared__ float red[2];
    if ((c & 31) == 0) red[c >> 5] = part;
    __syncthreads();
    if (c == 0) {
        float ss = d_gss[g];
        d_gss[g] = 0.f;
        float var = (ss - (red[0] + red[1])) / cnt;
        d_invd[g] = rsqrtf(PN_EPS + var);
    }
}

// ---------------- PairNorm apply (also writes fp16 shadow) -----------------
__global__ void __launch_bounds__(256) norm_kernel(const int* __restrict__ batch) {
    int idx = blockIdx.x * 256 + threadIdx.x;    // exactly NN*HV
    int row = idx >> 4, ln = idx & 15;
    int g = __ldg(batch + row);
    float4 hv = ((const float4*)d_h)[idx];
    float4 m = ((const float4*)d_mean)[g * HV + ln];
    float id = d_invd[g];
    hv.x = (hv.x - m.x) * id;
    hv.y = (hv.y - m.y) * id;
    hv.z = (hv.z - m.z) * id;
    hv.w = (hv.w - m.w) * id;
    ((float4*)d_h)[idx] = hv;
    ((uint2*)d_h16)[idx] = f4_to_h4(hv);
}

// ---------------- classifier; self-re-zeros pool ---------------------------
__global__ void cls_kernel(const float* __restrict__ W, const float* __restrict__ b,
                           float* __restrict__ out) {
    int g = blockIdx.x, c = threadIdx.x;     // 64 threads
    float p = d_pool[g * H + c];
    d_pool[g * H + c] = 0.f;
    float a = p * W[c * NOUT + 0];
    float bb = p * W[c * NOUT + 1];
    #pragma unroll
    for (int o = 16; o; o >>= 1) {
        a  += __shfl_down_sync(0xffffffffu, a, o);
        bb += __shfl_down_sync(0xffffffffu, bb, o);
    }
    __shared__ float sa[2], sb[2];
    if ((c & 31) == 0) { sa[c >> 5] = a; sb[c >> 5] = bb; }
    __syncthreads();
    if (c == 0) {
        out[g * NOUT + 0] = sa[0] + sa[1] + b[0];
        out[g * NOUT + 1] = sb[0] + sb[1] + b[1];
    }
}

// ---------------------------------------------------------------------------
extern "C" void kernel_launch(void* const* d_in, const int* in_sizes, int n_in,
                              void* d_out, int out_size) {
    const float* x        = (const float*)d_in[0];
    const int*   ei       = (const int*)  d_in[1];
    const float* eattr    = (const float*)d_in[2];
    const int*   batch    = (const int*)  d_in[3];
    const float* lin_W    = (const float*)d_in[4];
    const float* lin_b    = (const float*)d_in[5];
    const float* edge_W   = (const float*)d_in[6];
    const float* edge_b   = (const float*)d_in[7];
    const float* mlp_W1   = (const float*)d_in[8];
    const float* mlp_b1   = (const float*)d_in[9];
    const float* mbn_g    = (const float*)d_in[10];
    const float* mbn_b    = (const float*)d_in[11];
    const float* mbn_rm   = (const float*)d_in[12];
    const float* mbn_rv   = (const float*)d_in[13];
    const float* mlp_W2   = (const float*)d_in[14];
    const float* mlp_b2   = (const float*)d_in[15];
    const float* eps      = (const float*)d_in[16];
    const float* bn_g     = (const float*)d_in[17];
    const float* bn_b     = (const float*)d_in[18];
    const float* bn_rm    = (const float*)d_in[19];
    const float* bn_rv    = (const float*)d_in[20];
    const float* cls_W    = (const float*)d_in[21];
    const float* cls_b    = (const float*)d_in[22];
    float* out = (float*)d_out;

    count_kernel<<<2, 256>>>(batch);
    lin_in_kernel<<<NPAD / 16, 256>>>(x, lin_W, lin_b);

    for (int i = 0; i < NL; i++) {
        edge_kernel<<<NE / EPB, 256>>>(ei, eattr, edge_W + i * EDIM * H, edge_b + i * H);
        int do_pn = (i < NL - 1) ? 1 : 0;
        mlp_fused_kernel<<<NPAD / 64, 256>>>(
            mlp_W1 + i * H * H, mlp_b1 + i * H,
            mbn_g + i * H, mbn_b + i * H, mbn_rm + i * H, mbn_rv + i * H,
            mlp_W2 + i * H * H, mlp_b2 + i * H,
            bn_g + i * H, bn_b + i * H, bn_rm + i * H, bn_rv + i * H,
            eps + i, batch, do_pn);
        if (do_pn) {
            meaninv_kernel<<<NG, H>>>();
            norm_kernel<<<(NN * HV) / 256, 256>>>(batch);
        }
    }

    cls_kernel<<<NG, H>>>(cls_W, cls_b, out);
}

// round 14
// speedup vs baseline: 1.0132x; 1.0132x over previous
#include <cuda_runtime.h>
#include <cuda_fp16.h>
#include <math.h>

#define NN    50000
#define NE    800000
#define INF_  32
#define H     64
#define HV    16      // H/4 (float4 lanes per row)
#define EDIM  4
#define NL    3
#define NG    512
#define NOUT  2
#define NPAD  50048   // 782 * 64
#define BN_EPS 1e-5f
#define PN_EPS 1e-5f
#define EPB   128     // edges per block in edge_kernel (8 per 16-thread group)
#define ZPAD  68      // padded row stride (floats) for conflict-free mma frags

// ---------------- persistent device scratch (zero-initialized at load) -----
__device__ float d_h[NPAD * H];
__device__ __align__(16) __half d_h16[NPAD * H];   // fp16 shadow for gathers
__device__ float d_agg[NPAD * H];
__device__ float d_gsum[NG * H];
__device__ float d_gss[NG];
__device__ float d_gcnt[NG];
__device__ float d_mean[NG * H];
__device__ float d_invd[NG];
__device__ float d_pool[NG * H];

// 16-byte vector reduction to global (sm_90+)
__device__ __forceinline__ void red_add4(float4* a, float4 v) {
    asm volatile("red.global.add.v4.f32 [%0], {%1,%2,%3,%4};"
                 :: "l"(a), "f"(v.x), "f"(v.y), "f"(v.z), "f"(v.w) : "memory");
}
__device__ __forceinline__ void red_add2(float2* a, float v0, float v1) {
    asm volatile("red.global.add.v2.f32 [%0], {%1,%2};"
                 :: "l"(a), "f"(v0), "f"(v1) : "memory");
}

__device__ __forceinline__ float4 f4zero() { return make_float4(0.f, 0.f, 0.f, 0.f); }

__device__ __forceinline__ void f4fma(float4& acc, float s, const float4 w) {
    acc.x = fmaf(s, w.x, acc.x);
    acc.y = fmaf(s, w.y, acc.y);
    acc.z = fmaf(s, w.z, acc.z);
    acc.w = fmaf(s, w.w, acc.w);
}

__device__ __forceinline__ float4 f4relu_add(float4 a, float4 b) {
    return make_float4(fmaxf(a.x + b.x, 0.f), fmaxf(a.y + b.y, 0.f),
                       fmaxf(a.z + b.z, 0.f), fmaxf(a.w + b.w, 0.f));
}

__device__ __forceinline__ uint2 f4_to_h4(float4 v) {
    __half2 lo = __floats2half2_rn(v.x, v.y);
    __half2 hi = __floats2half2_rn(v.z, v.w);
    uint2 r;
    r.x = *reinterpret_cast<unsigned*>(&lo);
    r.y = *reinterpret_cast<unsigned*>(&hi);
    return r;
}

__device__ __forceinline__ float4 h4_to_f4(uint2 u) {
    __half2 lo = *reinterpret_cast<__half2*>(&u.x);
    __half2 hi = *reinterpret_cast<__half2*>(&u.y);
    float2 a = __half22float2(lo);
    float2 b = __half22float2(hi);
    return make_float4(a.x, a.y, b.x, b.y);
}

__device__ __forceinline__ float tf32r(float x) {
    unsigned u;
    asm("cvt.rna.tf32.f32 %0, %1;" : "=r"(u) : "f"(x));
    return __uint_as_float(u);
}
__device__ __forceinline__ float4 tf32r4(float4 v) {
    return make_float4(tf32r(v.x), tf32r(v.y), tf32r(v.z), tf32r(v.w));
}

__device__ __forceinline__ void mma16n8k8(float c[4], unsigned a0, unsigned a1,
                                          unsigned a2, unsigned a3,
                                          unsigned b0, unsigned b1) {
    asm volatile(
        "mma.sync.aligned.m16n8k8.row.col.f32.tf32.tf32.f32 "
        "{%0,%1,%2,%3}, {%4,%5,%6,%7}, {%8,%9}, {%0,%1,%2,%3};"
        : "+f"(c[0]), "+f"(c[1]), "+f"(c[2]), "+f"(c[3])
        : "r"(a0), "r"(a1), "r"(a2), "r"(a3), "r"(b0), "r"(b1));
}

// ---------------- counts: batch is sorted -> binary search per graph -------
__global__ void count_kernel(const int* __restrict__ batch) {
    int g = blockIdx.x * blockDim.x + threadIdx.x;
    if (g >= NG) return;
    int lo = 0, hi = NN;
    while (lo < hi) { int m = (lo + hi) >> 1; if (batch[m] < g) lo = m + 1; else hi = m; }
    int s = lo;
    lo = 0; hi = NN;
    while (lo < hi) { int m = (lo + hi) >> 1; if (batch[m] < g + 1) lo = m + 1; else hi = m; }
    d_gcnt[g] = fmaxf((float)(lo - s), 1.0f);
}

// ---------------- input linear: h = x @ W_in + b ; zeroes d_agg; h16 -------
__global__ void __launch_bounds__(256) lin_in_kernel(const float* __restrict__ x,
                                                     const float* __restrict__ W,
                                                     const float* __restrict__ b) {
    __shared__ __align__(16) float4 Ws[INF_ * HV];
    __shared__ __align__(16) float4 bs[HV];
    int t = threadIdx.x;
    for (int j = t; j < INF_ * HV; j += 256) Ws[j] = ((const float4*)W)[j];
    if (t < HV) bs[t] = ((const float4*)b)[t];
    __syncthreads();

    int lane = t & 15, rloc = t >> 4;
    int row = blockIdx.x * 16 + rloc;

    ((float4*)d_agg)[row * HV + lane] = f4zero();

    if (row < NN) {
        float4 acc = bs[lane];
        const float* xr = x + row * INF_;
        #pragma unroll
        for (int k = 0; k < INF_; k++) {
            float xv = __ldg(xr + k);
            f4fma(acc, xv, Ws[k * HV + lane]);
        }
        ((float4*)d_h)[row * HV + lane] = acc;
        ((uint2*)d_h16)[row * HV + lane] = f4_to_h4(acc);
    }
}

// ---------------- edge kernel: agg[dst] += relu(h16[src] + ea @ We + be) ---
__global__ void __launch_bounds__(256) edge_kernel(const int* __restrict__ ei,
                                                   const float* __restrict__ eattr,
                                                   const float* __restrict__ eW,
                                                   const float* __restrict__ eb) {
    __shared__ __align__(16) float4 Ws[EDIM * HV];
    __shared__ __align__(16) float4 bs[HV];
    int t = threadIdx.x;
    if (t < EDIM * HV) Ws[t] = ((const float4*)eW)[t];
    if (t < HV) bs[t] = ((const float4*)eb)[t];
    __syncthreads();

    int e0   = blockIdx.x * EPB + (t >> 4) * 8;
    int lane = t & 15;

    int4 sa = __ldg((const int4*)(ei) + (e0 >> 2));
    int4 sb = __ldg((const int4*)(ei) + (e0 >> 2) + 1);
    int4 da = __ldg((const int4*)(ei + NE) + (e0 >> 2));
    int4 db = __ldg((const int4*)(ei + NE) + (e0 >> 2) + 1);
    int src[8] = {sa.x, sa.y, sa.z, sa.w, sb.x, sb.y, sb.z, sb.w};
    int dst[8] = {da.x, da.y, da.z, da.w, db.x, db.y, db.z, db.w};

    uint2 hr[8];
    #pragma unroll
    for (int j = 0; j < 8; j++)
        hr[j] = __ldg((const uint2*)d_h16 + src[j] * HV + lane);

    float4 a[8];
    #pragma unroll
    for (int j = 0; j < 8; j++) a[j] = __ldg((const float4*)eattr + e0 + j);

    float4 w0 = Ws[0 * HV + lane], w1 = Ws[1 * HV + lane];
    float4 w2 = Ws[2 * HV + lane], w3 = Ws[3 * HV + lane];
    float4 bv = bs[lane];

    #pragma unroll
    for (int j = 0; j < 8; j++) {
        float4 v = bv;
        f4fma(v, a[j].x, w0);
        f4fma(v, a[j].y, w1);
        f4fma(v, a[j].z, w2);
        f4fma(v, a[j].w, w3);
        float4 m = f4relu_add(v, h4_to_f4(hr[j]));
        red_add4((float4*)d_agg + dst[j] * HV + lane, m);
    }
}

// ---------------- fused node MLP via tf32 mma.sync (B-resident ILP) --------
// z = (1+eps)*h + agg ; t = relu(BN1(z@W1+b1)) [smem] ; h' = relu(BN2(t@W2+b2))
// A (zs) row-major [64][ZPAD], B (WsT) n-major [64][ZPAD]. 64-row tile/block.
// Warp w: rows m0=(w&3)*16, cols n0=(w>>2)*32 (4 n-tiles of 8).
// All 64 B fragments preloaded into registers per GEMM; __launch_bounds__(256,2)
// gives 128 regs/thread so they stay resident.
__global__ void __launch_bounds__(256, 2) mlp_fused_kernel(
    const float* __restrict__ W1, const float* __restrict__ b1,
    const float* __restrict__ g1, const float* __restrict__ be1,
    const float* __restrict__ rm1, const float* __restrict__ rv1,
    const float* __restrict__ W2, const float* __restrict__ b2,
    const float* __restrict__ g2, const float* __restrict__ be2,
    const float* __restrict__ rm2, const float* __restrict__ rv2,
    const float* __restrict__ epsp, const int* __restrict__ batch, int do_pn)
{
    __shared__ __align__(16) float zs[64 * ZPAD];
    __shared__ __align__(16) float WsT[64 * ZPAD];
    __shared__ __align__(16) float s1s[H], s2s[H], bias1[H], bias2[H];

    int t = threadIdx.x;
    int lane = t & 31, w = t >> 5;
    int tig = lane & 3, g = lane >> 2;
    int m0 = (w & 3) * 16, n0 = (w >> 2) * 32;
    int R0 = blockIdx.x * 64;
    float epv = 1.0f + __ldg(epsp);

    // --- phase (a): batch global loads; t<64 computes BN folds -------------
    float4 wv[4], hvv[4], avv[4];
    #pragma unroll
    for (int s = 0; s < 4; s++) {
        wv[s]  = __ldg((const float4*)W1 + t + 256 * s);
        hvv[s] = __ldg((const float4*)d_h + R0 * HV + t + 256 * s);
        avv[s] = __ldg((const float4*)d_agg + R0 * HV + t + 256 * s);
    }
    if (t < H) {
        float s1 = __ldg(g1 + t) * rsqrtf(__ldg(rv1 + t) + BN_EPS);
        s1s[t] = s1;
        bias1[t] = fmaf(__ldg(b1 + t) - __ldg(rm1 + t), s1, __ldg(be1 + t));
        float s2 = __ldg(g2 + t) * rsqrtf(__ldg(rv2 + t) + BN_EPS);
        s2s[t] = s2;
        bias2[t] = fmaf(__ldg(b2 + t) - __ldg(rm2 + t), s2, __ldg(be2 + t));
    }
    __syncthreads();

    // --- phase (b): stage scaled W1 (transposed, tf32) and z (tf32) --------
    #pragma unroll
    for (int s = 0; s < 4; s++) {
        int idx = t + 256 * s;                 // float4 index in [0,1024)
        int k  = idx >> 4;                     // W row (k), z row
        int n4 = (idx & 15) * 4;               // W col base / z k base
        float4 sc = *(const float4*)&s1s[n4];
        float4 ww = wv[s];
        WsT[(n4 + 0) * ZPAD + k] = tf32r(ww.x * sc.x);
        WsT[(n4 + 1) * ZPAD + k] = tf32r(ww.y * sc.y);
        WsT[(n4 + 2) * ZPAD + k] = tf32r(ww.z * sc.z);
        WsT[(n4 + 3) * ZPAD + k] = tf32r(ww.w * sc.w);
        float4 hv = hvv[s], av = avv[s];
        float4 z = make_float4(fmaf(epv, hv.x, av.x), fmaf(epv, hv.y, av.y),
                               fmaf(epv, hv.z, av.z), fmaf(epv, hv.w, av.w));
        *(float4*)&zs[k * ZPAD + n4] = tf32r4(z);
        if (do_pn) ((float4*)d_agg)[R0 * HV + idx] = f4zero();
    }
    __syncthreads();

    // --- GEMM1: preload all B frags, then stream A ------------------------
    float c[4][4];
    unsigned bf[4][8][2];
    #pragma unroll
    for (int nt = 0; nt < 4; nt++) {
        const float* brow = &WsT[(n0 + nt * 8 + g) * ZPAD + tig];
        #pragma unroll
        for (int kk = 0; kk < 8; kk++) {
            bf[nt][kk][0] = __float_as_uint(brow[kk * 8]);
            bf[nt][kk][1] = __float_as_uint(brow[kk * 8 + 4]);
        }
    }
    #pragma unroll
    for (int nt = 0; nt < 4; nt++)
        c[nt][0] = c[nt][1] = c[nt][2] = c[nt][3] = 0.f;
    {
        const float* arow0 = &zs[(m0 + g) * ZPAD + tig];
        const float* arow1 = &zs[(m0 + g + 8) * ZPAD + tig];
        #pragma unroll
        for (int kk = 0; kk < 8; kk++) {
            unsigned a0 = __float_as_uint(arow0[kk * 8]);
            unsigned a1 = __float_as_uint(arow1[kk * 8]);
            unsigned a2 = __float_as_uint(arow0[kk * 8 + 4]);
            unsigned a3 = __float_as_uint(arow1[kk * 8 + 4]);
            #pragma unroll
            for (int nt = 0; nt < 4; nt++)
                mma16n8k8(c[nt], a0, a1, a2, a3, bf[nt][kk][0], bf[nt][kk][1]);
        }
    }

    // prefetch W2 while waiting
    #pragma unroll
    for (int s = 0; s < 4; s++) wv[s] = __ldg((const float4*)W2 + t + 256 * s);

    __syncthreads();   // GEMM1 reads of zs/WsT complete

    // --- phase (d): stage t -> zs (relu+bias1, tf32) and scaled W2T --------
    #pragma unroll
    for (int nt = 0; nt < 4; nt++) {
        int col = n0 + nt * 8 + 2 * tig;
        float bA0 = bias1[col], bA1 = bias1[col + 1];
        float v0 = fmaxf(c[nt][0] + bA0, 0.f), v1 = fmaxf(c[nt][1] + bA1, 0.f);
        float v2 = fmaxf(c[nt][2] + bA0, 0.f), v3 = fmaxf(c[nt][3] + bA1, 0.f);
        float2* p0 = (float2*)&zs[(m0 + g) * ZPAD + col];
        float2* p1 = (float2*)&zs[(m0 + g + 8) * ZPAD + col];
        *p0 = make_float2(tf32r(v0), tf32r(v1));
        *p1 = make_float2(tf32r(v2), tf32r(v3));
    }
    #pragma unroll
    for (int s = 0; s < 4; s++) {
        int idx = t + 256 * s;
        int k  = idx >> 4;
        int n4 = (idx & 15) * 4;
        float4 sc = *(const float4*)&s2s[n4];
        float4 ww = wv[s];
        WsT[(n4 + 0) * ZPAD + k] = tf32r(ww.x * sc.x);
        WsT[(n4 + 1) * ZPAD + k] = tf32r(ww.y * sc.y);
        WsT[(n4 + 2) * ZPAD + k] = tf32r(ww.z * sc.z);
        WsT[(n4 + 3) * ZPAD + k] = tf32r(ww.w * sc.w);
    }
    __syncthreads();

    // --- GEMM2: same B-resident pattern ------------------------------------
    #pragma unroll
    for (int nt = 0; nt < 4; nt++) {
        const float* brow = &WsT[(n0 + nt * 8 + g) * ZPAD + tig];
        #pragma unroll
        for (int kk = 0; kk < 8; kk++) {
            bf[nt][kk][0] = __float_as_uint(brow[kk * 8]);
            bf[nt][kk][1] = __float_as_uint(brow[kk * 8 + 4]);
        }
    }
    #pragma unroll
    for (int nt = 0; nt < 4; nt++)
        c[nt][0] = c[nt][1] = c[nt][2] = c[nt][3] = 0.f;
    {
        const float* arow0 = &zs[(m0 + g) * ZPAD + tig];
        const float* arow1 = &zs[(m0 + g + 8) * ZPAD + tig];
        #pragma unroll
        for (int kk = 0; kk < 8; kk++) {
            unsigned a0 = __float_as_uint(arow0[kk * 8]);
            unsigned a1 = __float_as_uint(arow1[kk * 8]);
            unsigned a2 = __float_as_uint(arow0[kk * 8 + 4]);
            unsigned a3 = __float_as_uint(arow1[kk * 8 + 4]);
            #pragma unroll
            for (int nt = 0; nt < 4; nt++)
                mma16n8k8(c[nt], a0, a1, a2, a3, bf[nt][kk][0], bf[nt][kk][1]);
        }
    }

    // --- epilogue: BN2+ReLU, store h, PN stats / pool ----------------------
    int rowA = R0 + m0 + g;
    int rowB = rowA + 8;
    bool okA = rowA < NN, okB = rowB < NN;
    int ggA = okA ? __ldg(batch + rowA) : 0;
    int ggB = okB ? __ldg(batch + rowB) : 0;
    float sqA = 0.f, sqB = 0.f;

    #pragma unroll
    for (int nt = 0; nt < 4; nt++) {
        int col = n0 + nt * 8 + 2 * tig;
        float bA0 = bias2[col], bA1 = bias2[col + 1];
        float v0 = fmaxf(c[nt][0] + bA0, 0.f), v1 = fmaxf(c[nt][1] + bA1, 0.f);
        float v2 = fmaxf(c[nt][2] + bA0, 0.f), v3 = fmaxf(c[nt][3] + bA1, 0.f);
        if (okA) *(float2*)&d_h[rowA * H + col] = make_float2(v0, v1);
        if (okB) *(float2*)&d_h[rowB * H + col] = make_float2(v2, v3);
        if (do_pn) {
            if (okA) red_add2((float2*)&d_gsum[ggA * H + col], v0, v1);
            if (okB) red_add2((float2*)&d_gsum[ggB * H + col], v2, v3);
            sqA = fmaf(v0, v0, fmaf(v1, v1, sqA));
            sqB = fmaf(v2, v2, fmaf(v3, v3, sqB));
        } else {
            if (okA) red_add2((float2*)&d_pool[ggA * H + col], v0, v1);
            if (okB) red_add2((float2*)&d_pool[ggB * H + col], v2, v3);
        }
    }
    if (do_pn) {
        sqA += __shfl_xor_sync(0xffffffffu, sqA, 1);
        sqA += __shfl_xor_sync(0xffffffffu, sqA, 2);
        sqB += __shfl_xor_sync(0xffffffffu, sqB, 1);
        sqB += __shfl_xor_sync(0xffffffffu, sqB, 2);
        if (tig == 0) {
            if (okA) atomicAdd(&d_gss[ggA], sqA);
            if (okB) atomicAdd(&d_gss[ggB], sqB);
        }
    }
}

// ---------------- PairNorm per-graph mean & inverse denom; self-re-zeros ---
__global__ void meaninv_kernel() {
    int g = blockIdx.x, c = threadIdx.x;     // 64 threads
    float cnt = d_gcnt[g];
    float s = d_gsum[g * H + c];
    d_gsum[g * H + c] = 0.f;
    float mean = s / cnt;
    d_mean[g * H + c] = mean;
    float part = mean * s;
    #pragma unroll
    for (int o = 16; o; o >>= 1) part += __shfl_down_sync(0xffffffffu, part, o);
    __shared__ float red[2];
    if ((c & 31) == 0) red[c >> 5] = part;
    __syncthreads();
    if (c == 0) {
        float ss = d_gss[g];
        d_gss[g] = 0.f;
        float var = (ss - (red[0] + red[1])) / cnt;
        d_invd[g] = rsqrtf(PN_EPS + var);
    }
}

// ---------------- PairNorm apply (also writes fp16 shadow) -----------------
__global__ void __launch_bounds__(256) norm_kernel(const int* __restrict__ batch) {
    int idx = blockIdx.x * 256 + threadIdx.x;    // exactly NN*HV
    int row = idx >> 4, ln = idx & 15;
    int g = __ldg(batch + row);
    float4 hv = ((const float4*)d_h)[idx];
    float4 m = ((const float4*)d_mean)[g * HV + ln];
    float id = d_invd[g];
    hv.x = (hv.x - m.x) * id;
    hv.y = (hv.y - m.y) * id;
    hv.z = (hv.z - m.z) * id;
    hv.w = (hv.w - m.w) * id;
    ((float4*)d_h)[idx] = hv;
    ((uint2*)d_h16)[idx] = f4_to_h4(hv);
}

// ---------------- classifier; self-re-zeros pool ---------------------------
__global__ void cls_kernel(const float* __restrict__ W, const float* __restrict__ b,
                           float* __restrict__ out) {
    int g = blockIdx.x, c = threadIdx.x;     // 64 threads
    float p = d_pool[g * H + c];
    d_pool[g * H + c] = 0.f;
    float a = p * W[c * NOUT + 0];
    float bb = p * W[c * NOUT + 1];
    #pragma unroll
    for (int o = 16; o; o >>= 1) {
        a  += __shfl_down_sync(0xffffffffu, a, o);
        bb += __shfl_down_sync(0xffffffffu, bb, o);
    }
    __shared__ float sa[2], sb[2];
    if ((c & 31) == 0) { sa[c >> 5] = a; sb[c >> 5] = bb; }
    __syncthreads();
    if (c == 0) {
        out[g * NOUT + 0] = sa[0] + sa[1] + b[0];
        out[g * NOUT + 1] = sb[0] + sb[1] + b[1];
    }
}

// ---------------------------------------------------------------------------
extern "C" void kernel_launch(void* const* d_in, const int* in_sizes, int n_in,
                              void* d_out, int out_size) {
    const float* x        = (const float*)d_in[0];
    const int*   ei       = (const int*)  d_in[1];
    const float* eattr    = (const float*)d_in[2];
    const int*   batch    = (const int*)  d_in[3];
    const float* lin_W    = (const float*)d_in[4];
    const float* lin_b    = (const float*)d_in[5];
    const float* edge_W   = (const float*)d_in[6];
    const float* edge_b   = (const float*)d_in[7];
    const float* mlp_W1   = (const float*)d_in[8];
    const float* mlp_b1   = (const float*)d_in[9];
    const float* mbn_g    = (const float*)d_in[10];
    const float* mbn_b    = (const float*)d_in[11];
    const float* mbn_rm   = (const float*)d_in[12];
    const float* mbn_rv   = (const float*)d_in[13];
    const float* mlp_W2   = (const float*)d_in[14];
    const float* mlp_b2   = (const float*)d_in[15];
    const float* eps      = (const float*)d_in[16];
    const float* bn_g     = (const float*)d_in[17];
    const float* bn_b     = (const float*)d_in[18];
    const float* bn_rm    = (const float*)d_in[19];
    const float* bn_rv    = (const float*)d_in[20];
    const float* cls_W    = (const float*)d_in[21];
    const float* cls_b    = (const float*)d_in[22];
    float* out = (float*)d_out;

    count_kernel<<<2, 256>>>(batch);
    lin_in_kernel<<<NPAD / 16, 256>>>(x, lin_W, lin_b);

    for (int i = 0; i < NL; i++) {
        edge_kernel<<<NE / EPB, 256>>>(ei, eattr, edge_W + i * EDIM * H, edge_b + i * H);
        int do_pn = (i < NL - 1) ? 1 : 0;
        mlp_fused_kernel<<<NPAD / 64, 256>>>(
            mlp_W1 + i * H * H, mlp_b1 + i * H,
            mbn_g + i * H, mbn_b + i * H, mbn_rm + i * H, mbn_rv + i * H,
            mlp_W2 + i * H * H, mlp_b2 + i * H,
            bn_g + i * H, bn_b + i * H, bn_rm + i * H, bn_rv + i * H,
            eps + i, batch, do_pn);
        if (do_pn) {
            meaninv_kernel<<<NG, H>>>();
            norm_kernel<<<(NN * HV) / 256, 256>>>(batch);
        }
    }

    cls_kernel<<<NG, H>>>(cls_W, cls_b, out);
}

// round 15
// speedup vs baseline: 1.1182x; 1.1037x over previous
#include <cuda_runtime.h>
#include <cuda_fp16.h>
#include <math.h>

#define NN    50000
#define NE    800000
#define INF_  32
#define H     64
#define HV    16      // H/4 (float4 lanes per row)
#define EDIM  4
#define NL    3
#define NG    512
#define NOUT  2
#define NPAD  50048   // 782 * 64
#define BN_EPS 1e-5f
#define PN_EPS 1e-5f
#define EPB   128     // edges per block in edge_kernel (8 per 16-thread group)
#define KP    72      // padded halves per row in mma smem tiles (36 words: 4g+tig banks)

// ---------------- persistent device scratch (zero-initialized at load) -----
__device__ float d_h[NPAD * H];
__device__ __align__(16) __half d_h16[NPAD * H];   // fp16 shadow for gathers
__device__ float d_agg[NPAD * H];
__device__ float d_gsum[NG * H];
__device__ float d_gss[NG];
__device__ float d_gcnt[NG];
__device__ float d_mean[NG * H];
__device__ float d_invd[NG];
__device__ float d_pool[NG * H];

// 16-byte vector reduction to global (sm_90+)
__device__ __forceinline__ void red_add4(float4* a, float4 v) {
    asm volatile("red.global.add.v4.f32 [%0], {%1,%2,%3,%4};"
                 :: "l"(a), "f"(v.x), "f"(v.y), "f"(v.z), "f"(v.w) : "memory");
}
__device__ __forceinline__ void red_add2(float2* a, float v0, float v1) {
    asm volatile("red.global.add.v2.f32 [%0], {%1,%2};"
                 :: "l"(a), "f"(v0), "f"(v1) : "memory");
}

__device__ __forceinline__ float4 f4zero() { return make_float4(0.f, 0.f, 0.f, 0.f); }

__device__ __forceinline__ void f4fma(float4& acc, float s, const float4 w) {
    acc.x = fmaf(s, w.x, acc.x);
    acc.y = fmaf(s, w.y, acc.y);
    acc.z = fmaf(s, w.z, acc.z);
    acc.w = fmaf(s, w.w, acc.w);
}

__device__ __forceinline__ float4 f4relu_add(float4 a, float4 b) {
    return make_float4(fmaxf(a.x + b.x, 0.f), fmaxf(a.y + b.y, 0.f),
                       fmaxf(a.z + b.z, 0.f), fmaxf(a.w + b.w, 0.f));
}

__device__ __forceinline__ uint2 f4_to_h4(float4 v) {
    __half2 lo = __floats2half2_rn(v.x, v.y);
    __half2 hi = __floats2half2_rn(v.z, v.w);
    uint2 r;
    r.x = *reinterpret_cast<unsigned*>(&lo);
    r.y = *reinterpret_cast<unsigned*>(&hi);
    return r;
}

__device__ __forceinline__ float4 h4_to_f4(uint2 u) {
    __half2 lo = *reinterpret_cast<__half2*>(&u.x);
    __half2 hi = *reinterpret_cast<__half2*>(&u.y);
    float2 a = __half22float2(lo);
    float2 b = __half22float2(hi);
    return make_float4(a.x, a.y, b.x, b.y);
}

// fp16 tensor-core mma: D(f32) += A(f16,row) * B(f16,col), m16n8k16
__device__ __forceinline__ void mma_f16(float c[4], unsigned a0, unsigned a1,
                                        unsigned a2, unsigned a3,
                                        unsigned b0, unsigned b1) {
    asm volatile(
        "mma.sync.aligned.m16n8k16.row.col.f32.f16.f16.f32 "
        "{%0,%1,%2,%3}, {%4,%5,%6,%7}, {%8,%9}, {%0,%1,%2,%3};"
        : "+f"(c[0]), "+f"(c[1]), "+f"(c[2]), "+f"(c[3])
        : "r"(a0), "r"(a1), "r"(a2), "r"(a3), "r"(b0), "r"(b1));
}

// ---------------- counts: batch is sorted -> binary search per graph -------
__global__ void count_kernel(const int* __restrict__ batch) {
    int g = blockIdx.x * blockDim.x + threadIdx.x;
    if (g >= NG) return;
    int lo = 0, hi = NN;
    while (lo < hi) { int m = (lo + hi) >> 1; if (batch[m] < g) lo = m + 1; else hi = m; }
    int s = lo;
    lo = 0; hi = NN;
    while (lo < hi) { int m = (lo + hi) >> 1; if (batch[m] < g + 1) lo = m + 1; else hi = m; }
    d_gcnt[g] = fmaxf((float)(lo - s), 1.0f);
}

// ---------------- input linear: h = x @ W_in + b ; zeroes d_agg; h16 -------
__global__ void __launch_bounds__(256) lin_in_kernel(const float* __restrict__ x,
                                                     const float* __restrict__ W,
                                                     const float* __restrict__ b) {
    __shared__ __align__(16) float4 Ws[INF_ * HV];
    __shared__ __align__(16) float4 bs[HV];
    int t = threadIdx.x;
    for (int j = t; j < INF_ * HV; j += 256) Ws[j] = ((const float4*)W)[j];
    if (t < HV) bs[t] = ((const float4*)b)[t];
    __syncthreads();

    int lane = t & 15, rloc = t >> 4;
    int row = blockIdx.x * 16 + rloc;

    ((float4*)d_agg)[row * HV + lane] = f4zero();

    if (row < NN) {
        float4 acc = bs[lane];
        const float* xr = x + row * INF_;
        #pragma unroll
        for (int k = 0; k < INF_; k++) {
            float xv = __ldg(xr + k);
            f4fma(acc, xv, Ws[k * HV + lane]);
        }
        ((float4*)d_h)[row * HV + lane] = acc;
        ((uint2*)d_h16)[row * HV + lane] = f4_to_h4(acc);
    }
}

// ---------------- edge kernel: agg[dst] += relu(h16[src] + ea @ We + be) ---
__global__ void __launch_bounds__(256) edge_kernel(const int* __restrict__ ei,
                                                   const float* __restrict__ eattr,
                                                   const float* __restrict__ eW,
                                                   const float* __restrict__ eb) {
    __shared__ __align__(16) float4 Ws[EDIM * HV];
    __shared__ __align__(16) float4 bs[HV];
    int t = threadIdx.x;
    if (t < EDIM * HV) Ws[t] = ((const float4*)eW)[t];
    if (t < HV) bs[t] = ((const float4*)eb)[t];
    __syncthreads();

    int e0   = blockIdx.x * EPB + (t >> 4) * 8;
    int lane = t & 15;

    int4 sa = __ldg((const int4*)(ei) + (e0 >> 2));
    int4 sb = __ldg((const int4*)(ei) + (e0 >> 2) + 1);
    int4 da = __ldg((const int4*)(ei + NE) + (e0 >> 2));
    int4 db = __ldg((const int4*)(ei + NE) + (e0 >> 2) + 1);
    int src[8] = {sa.x, sa.y, sa.z, sa.w, sb.x, sb.y, sb.z, sb.w};
    int dst[8] = {da.x, da.y, da.z, da.w, db.x, db.y, db.z, db.w};

    uint2 hr[8];
    #pragma unroll
    for (int j = 0; j < 8; j++)
        hr[j] = __ldg((const uint2*)d_h16 + src[j] * HV + lane);

    float4 a[8];
    #pragma unroll
    for (int j = 0; j < 8; j++) a[j] = __ldg((const float4*)eattr + e0 + j);

    float4 w0 = Ws[0 * HV + lane], w1 = Ws[1 * HV + lane];
    float4 w2 = Ws[2 * HV + lane], w3 = Ws[3 * HV + lane];
    float4 bv = bs[lane];

    #pragma unroll
    for (int j = 0; j < 8; j++) {
        float4 v = bv;
        f4fma(v, a[j].x, w0);
        f4fma(v, a[j].y, w1);
        f4fma(v, a[j].z, w2);
        f4fma(v, a[j].w, w3);
        float4 m = f4relu_add(v, h4_to_f4(hr[j]));
        red_add4((float4*)d_agg + dst[j] * HV + lane, m);
    }
}

// ---------------- fused node MLP via fp16 mma (f32 accumulate) -------------
// z = (1+eps)*h + agg ; t = relu(BN1(z@W1+b1)) [smem] ; h' = relu(BN2(t@W2+b2))
// A (zs_h) row-major [64][KP] halves, B (WT_h) n-major [64][KP] halves.
// 64-row tile; warp w: rows m0=(w&3)*16, cols n0=(w>>2)*32.
// W staging: thread owns column n=t&63, k-quarter q=t>>6 (coalesced LDG,
// per-thread BN fold, no barrier dependency).
__global__ void __launch_bounds__(256) mlp_fused_kernel(
    const float* __restrict__ W1, const float* __restrict__ b1,
    const float* __restrict__ g1, const float* __restrict__ be1,
    const float* __restrict__ rm1, const float* __restrict__ rv1,
    const float* __restrict__ W2, const float* __restrict__ b2,
    const float* __restrict__ g2, const float* __restrict__ be2,
    const float* __restrict__ rm2, const float* __restrict__ rv2,
    const float* __restrict__ epsp, const int* __restrict__ batch, int do_pn)
{
    __shared__ __align__(16) __half zs_h[64 * KP];
    __shared__ __align__(16) __half WT_h[64 * KP];
    __shared__ float bias1[H], bias2[H];

    int t = threadIdx.x;
    int lane = t & 31, w = t >> 5;
    int tig = lane & 3, g = lane >> 2;
    int m0 = (w & 3) * 16, n0 = (w >> 2) * 32;
    int R0 = blockIdx.x * 64;
    float epv = 1.0f + __ldg(epsp);

    // --- epilogue biases (t<64) --------------------------------------------
    if (t < H) {
        float s1 = __ldg(g1 + t) * rsqrtf(__ldg(rv1 + t) + BN_EPS);
        bias1[t] = fmaf(__ldg(b1 + t) - __ldg(rm1 + t), s1, __ldg(be1 + t));
        float s2 = __ldg(g2 + t) * rsqrtf(__ldg(rv2 + t) + BN_EPS);
        bias2[t] = fmaf(__ldg(b2 + t) - __ldg(rm2 + t), s2, __ldg(be2 + t));
    }

    // --- W1 staging: thread owns column n, k-range [16q,16q+16) ------------
    int n = t & 63, q = t >> 6;
    float s1n = __ldg(g1 + n) * rsqrtf(__ldg(rv1 + n) + BN_EPS);
    float wreg[16];
    #pragma unroll
    for (int j = 0; j < 16; j++)
        wreg[j] = __ldg(W1 + (q * 16 + j) * H + n);
    #pragma unroll
    for (int j = 0; j < 8; j++) {
        __half2 p = __floats2half2_rn(wreg[2 * j] * s1n, wreg[2 * j + 1] * s1n);
        *(__half2*)&WT_h[n * KP + q * 16 + 2 * j] = p;
    }

    // --- z staging: z = (1+eps)*h + agg, rounded to half -------------------
    #pragma unroll
    for (int s = 0; s < 4; s++) {
        int idx = t + 256 * s;
        int k  = idx >> 4;                 // row
        int n4 = (idx & 15) * 4;           // k-offset within row
        float4 hv = __ldg((const float4*)d_h + R0 * HV + idx);
        float4 av = __ldg((const float4*)d_agg + R0 * HV + idx);
        float4 z = make_float4(fmaf(epv, hv.x, av.x), fmaf(epv, hv.y, av.y),
                               fmaf(epv, hv.z, av.z), fmaf(epv, hv.w, av.w));
        *(uint2*)&zs_h[k * KP + n4] = f4_to_h4(z);
        if (do_pn) ((float4*)d_agg)[R0 * HV + idx] = f4zero();
    }
    __syncthreads();

    // --- GEMM1 --------------------------------------------------------------
    float c[4][4];
    #pragma unroll
    for (int nt = 0; nt < 4; nt++)
        c[nt][0] = c[nt][1] = c[nt][2] = c[nt][3] = 0.f;
    #pragma unroll
    for (int kk = 0; kk < 4; kk++) {
        int k0 = kk * 16;
        unsigned a0 = *(const unsigned*)&zs_h[(m0 + g) * KP + k0 + 2 * tig];
        unsigned a1 = *(const unsigned*)&zs_h[(m0 + g + 8) * KP + k0 + 2 * tig];
        unsigned a2 = *(const unsigned*)&zs_h[(m0 + g) * KP + k0 + 2 * tig + 8];
        unsigned a3 = *(const unsigned*)&zs_h[(m0 + g + 8) * KP + k0 + 2 * tig + 8];
        #pragma unroll
        for (int nt = 0; nt < 4; nt++) {
            const __half* bp = &WT_h[(n0 + nt * 8 + g) * KP + k0 + 2 * tig];
            unsigned b0 = *(const unsigned*)bp;
            unsigned b1 = *(const unsigned*)(bp + 8);
            mma_f16(c[nt], a0, a1, a2, a3, b0, b1);
        }
    }

    // --- W2 prefetch (overlaps barrier wait) -------------------------------
    float s2n = __ldg(g2 + n) * rsqrtf(__ldg(rv2 + n) + BN_EPS);
    #pragma unroll
    for (int j = 0; j < 16; j++)
        wreg[j] = __ldg(W2 + (q * 16 + j) * H + n);

    __syncthreads();   // all GEMM1 reads of zs_h/WT_h complete

    // --- stage t = relu(c + bias1) -> zs_h ; scaled W2 -> WT_h -------------
    #pragma unroll
    for (int nt = 0; nt < 4; nt++) {
        int col = n0 + nt * 8 + 2 * tig;
        float bA0 = bias1[col], bA1 = bias1[col + 1];
        float v0 = fmaxf(c[nt][0] + bA0, 0.f), v1 = fmaxf(c[nt][1] + bA1, 0.f);
        float v2 = fmaxf(c[nt][2] + bA0, 0.f), v3 = fmaxf(c[nt][3] + bA1, 0.f);
        *(__half2*)&zs_h[(m0 + g) * KP + col]     = __floats2half2_rn(v0, v1);
        *(__half2*)&zs_h[(m0 + g + 8) * KP + col] = __floats2half2_rn(v2, v3);
    }
    #pragma unroll
    for (int j = 0; j < 8; j++) {
        __half2 p = __floats2half2_rn(wreg[2 * j] * s2n, wreg[2 * j + 1] * s2n);
        *(__half2*)&WT_h[n * KP + q * 16 + 2 * j] = p;
    }
    __syncthreads();

    // --- GEMM2 --------------------------------------------------------------
    #pragma unroll
    for (int nt = 0; nt < 4; nt++)
        c[nt][0] = c[nt][1] = c[nt][2] = c[nt][3] = 0.f;
    #pragma unroll
    for (int kk = 0; kk < 4; kk++) {
        int k0 = kk * 16;
        unsigned a0 = *(const unsigned*)&zs_h[(m0 + g) * KP + k0 + 2 * tig];
        unsigned a1 = *(const unsigned*)&zs_h[(m0 + g + 8) * KP + k0 + 2 * tig];
        unsigned a2 = *(const unsigned*)&zs_h[(m0 + g) * KP + k0 + 2 * tig + 8];
        unsigned a3 = *(const unsigned*)&zs_h[(m0 + g + 8) * KP + k0 + 2 * tig + 8];
        #pragma unroll
        for (int nt = 0; nt < 4; nt++) {
            const __half* bp = &WT_h[(n0 + nt * 8 + g) * KP + k0 + 2 * tig];
            unsigned b0 = *(const unsigned*)bp;
            unsigned b1 = *(const unsigned*)(bp + 8);
            mma_f16(c[nt], a0, a1, a2, a3, b0, b1);
        }
    }

    // --- epilogue: BN2+ReLU, store h, PN stats / pool ----------------------
    int rowA = R0 + m0 + g;
    int rowB = rowA + 8;
    bool okA = rowA < NN, okB = rowB < NN;
    int ggA = okA ? __ldg(batch + rowA) : 0;
    int ggB = okB ? __ldg(batch + rowB) : 0;
    float sqA = 0.f, sqB = 0.f;

    #pragma unroll
    for (int nt = 0; nt < 4; nt++) {
        int col = n0 + nt * 8 + 2 * tig;
        float bA0 = bias2[col], bA1 = bias2[col + 1];
        float v0 = fmaxf(c[nt][0] + bA0, 0.f), v1 = fmaxf(c[nt][1] + bA1, 0.f);
        float v2 = fmaxf(c[nt][2] + bA0, 0.f), v3 = fmaxf(c[nt][3] + bA1, 0.f);
        if (okA) *(float2*)&d_h[rowA * H + col] = make_float2(v0, v1);
        if (okB) *(float2*)&d_h[rowB * H + col] = make_float2(v2, v3);
        if (do_pn) {
            if (okA) red_add2((float2*)&d_gsum[ggA * H + col], v0, v1);
            if (okB) red_add2((float2*)&d_gsum[ggB * H + col], v2, v3);
            sqA = fmaf(v0, v0, fmaf(v1, v1, sqA));
            sqB = fmaf(v2, v2, fmaf(v3, v3, sqB));
        } else {
            if (okA) red_add2((float2*)&d_pool[ggA * H + col], v0, v1);
            if (okB) red_add2((float2*)&d_pool[ggB * H + col], v2, v3);
        }
    }
    if (do_pn) {
        sqA += __shfl_xor_sync(0xffffffffu, sqA, 1);
        sqA += __shfl_xor_sync(0xffffffffu, sqA, 2);
        sqB += __shfl_xor_sync(0xffffffffu, sqB, 1);
        sqB += __shfl_xor_sync(0xffffffffu, sqB, 2);
        if (tig == 0) {
            if (okA) atomicAdd(&d_gss[ggA], sqA);
            if (okB) atomicAdd(&d_gss[ggB], sqB);
        }
    }
}

// ---------------- PairNorm per-graph mean & inverse denom; self-re-zeros ---
__global__ void meaninv_kernel() {
    int g = blockIdx.x, c = threadIdx.x;     // 64 threads
    float cnt = d_gcnt[g];
    float s = d_gsum[g * H + c];
    d_gsum[g * H + c] = 0.f;
    float mean = s / cnt;
    d_mean[g * H + c] = mean;
    float part = mean * s;
    #pragma unroll
    for (int o = 16; o; o >>= 1) part += __shfl_down_sync(0xffffffffu, part, o);
    __shared__ float red[2];
    if ((c & 31) == 0) red[c >> 5] = part;
    __syncthreads();
    if (c == 0) {
        float ss = d_gss[g];
        d_gss[g] = 0.f;
        float var = (ss - (red[0] + red[1])) / cnt;
        d_invd[g] = rsqrtf(PN_EPS + var);
    }
}

// ---------------- PairNorm apply (also writes fp16 shadow) -----------------
__global__ void __launch_bounds__(256) norm_kernel(const int* __restrict__ batch) {
    int idx = blockIdx.x * 256 + threadIdx.x;    // exactly NN*HV
    int row = idx >> 4, ln = idx & 15;
    int g = __ldg(batch + row);
    float4 hv = ((const float4*)d_h)[idx];
    float4 m = ((const float4*)d_mean)[g * HV + ln];
    float id = d_invd[g];
    hv.x = (hv.x - m.x) * id;
    hv.y = (hv.y - m.y) * id;
    hv.z = (hv.z - m.z) * id;
    hv.w = (hv.w - m.w) * id;
    ((float4*)d_h)[idx] = hv;
    ((uint2*)d_h16)[idx] = f4_to_h4(hv);
}

// ---------------- classifier; self-re-zeros pool ---------------------------
__global__ void cls_kernel(const float* __restrict__ W, const float* __restrict__ b,
                           float* __restrict__ out) {
    int g = blockIdx.x, c = threadIdx.x;     // 64 threads
    float p = d_pool[g * H + c];
    d_pool[g * H + c] = 0.f;
    float a = p * W[c * NOUT + 0];
    float bb = p * W[c * NOUT + 1];
    #pragma unroll
    for (int o = 16; o; o >>= 1) {
        a  += __shfl_down_sync(0xffffffffu, a, o);
        bb += __shfl_down_sync(0xffffffffu, bb, o);
    }
    __shared__ float sa[2], sb[2];
    if ((c & 31) == 0) { sa[c >> 5] = a; sb[c >> 5] = bb; }
    __syncthreads();
    if (c == 0) {
        out[g * NOUT + 0] = sa[0] + sa[1] + b[0];
        out[g * NOUT + 1] = sb[0] + sb[1] + b[1];
    }
}

// ---------------------------------------------------------------------------
extern "C" void kernel_launch(void* const* d_in, const int* in_sizes, int n_in,
                              void* d_out, int out_size) {
    const float* x        = (const float*)d_in[0];
    const int*   ei       = (const int*)  d_in[1];
    const float* eattr    = (const float*)d_in[2];
    const int*   batch    = (const int*)  d_in[3];
    const float* lin_W    = (const float*)d_in[4];
    const float* lin_b    = (const float*)d_in[5];
    const float* edge_W   = (const float*)d_in[6];
    const float* edge_b   = (const float*)d_in[7];
    const float* mlp_W1   = (const float*)d_in[8];
    const float* mlp_b1   = (const float*)d_in[9];
    const float* mbn_g    = (const float*)d_in[10];
    const float* mbn_b    = (const float*)d_in[11];
    const float* mbn_rm   = (const float*)d_in[12];
    const float* mbn_rv   = (const float*)d_in[13];
    const float* mlp_W2   = (const float*)d_in[14];
    const float* mlp_b2   = (const float*)d_in[15];
    const float* eps      = (const float*)d_in[16];
    const float* bn_g     = (const float*)d_in[17];
    const float* bn_b     = (const float*)d_in[18];
    const float* bn_rm    = (const float*)d_in[19];
    const float* bn_rv    = (const float*)d_in[20];
    const float* cls_W    = (const float*)d_in[21];
    const float* cls_b    = (const float*)d_in[22];
    float* out = (float*)d_out;

    count_kernel<<<2, 256>>>(batch);
    lin_in_kernel<<<NPAD / 16, 256>>>(x, lin_W, lin_b);

    for (int i = 0; i < NL; i++) {
        edge_kernel<<<NE / EPB, 256>>>(ei, eattr, edge_W + i * EDIM * H, edge_b + i * H);
        int do_pn = (i < NL - 1) ? 1 : 0;
        mlp_fused_kernel<<<NPAD / 64, 256>>>(
            mlp_W1 + i * H * H, mlp_b1 + i * H,
            mbn_g + i * H, mbn_b + i * H, mbn_rm + i * H, mbn_rv + i * H,
            mlp_W2 + i * H * H, mlp_b2 + i * H,
            bn_g + i * H, bn_b + i * H, bn_rm + i * H, bn_rv + i * H,
            eps + i, batch, do_pn);
        if (do_pn) {
            meaninv_kernel<<<NG, H>>>();
            norm_kernel<<<(NN * HV) / 256, 256>>>(batch);
        }
    }

    cls_kernel<<<NG, H>>>(cls_W, cls_b, out);
}

// round 16
// speedup vs baseline: 1.2112x; 1.0832x over previous
#include <cuda_runtime.h>
#include <cuda_fp16.h>
#include <math.h>

#define NN    50000
#define NE    800000
#define INF_  32
#define H     64
#define HV    16      // H/4 (float4 lanes per row)
#define EDIM  4
#define NL    3
#define NG    512
#define NOUT  2
#define NPAD  50048   // 782 * 64
#define BN_EPS 1e-5f
#define PN_EPS 1e-5f
#define EPB   128     // edges per block in edge_kernel (8 per 16-thread group)
#define KP    72      // padded halves per row in mma smem tiles

// ---------------- persistent device scratch (zero-initialized at load) -----
__device__ float d_h[NPAD * H];
__device__ __align__(16) __half d_h16[NPAD * H];    // fp16 shadow for gathers
__device__ __align__(16) __half d_agg16[NPAD * H];  // fp16 aggregation buffer
__device__ float d_gsum[NG * H];
__device__ float d_gss[NG];
__device__ float d_gcnt[NG];
__device__ float d_mean[NG * H];
__device__ float d_invd[NG];
__device__ float d_pool[NG * H];

// 16-byte vector reduction to global (sm_90+)
__device__ __forceinline__ void red_add4(float4* a, float4 v) {
    asm volatile("red.global.add.v4.f32 [%0], {%1,%2,%3,%4};"
                 :: "l"(a), "f"(v.x), "f"(v.y), "f"(v.z), "f"(v.w) : "memory");
}
__device__ __forceinline__ void red_add2(float2* a, float v0, float v1) {
    asm volatile("red.global.add.v2.f32 [%0], {%1,%2};"
                 :: "l"(a), "f"(v0), "f"(v1) : "memory");
}
// 8-byte fp16x2 vector reduction (4 halves)
__device__ __forceinline__ void red_addh4(uint2* a, uint2 v) {
    asm volatile("red.global.add.noftz.v2.f16x2 [%0], {%1,%2};"
                 :: "l"(a), "r"(v.x), "r"(v.y) : "memory");
}

__device__ __forceinline__ float4 f4zero() { return make_float4(0.f, 0.f, 0.f, 0.f); }

__device__ __forceinline__ void f4fma(float4& acc, float s, const float4 w) {
    acc.x = fmaf(s, w.x, acc.x);
    acc.y = fmaf(s, w.y, acc.y);
    acc.z = fmaf(s, w.z, acc.z);
    acc.w = fmaf(s, w.w, acc.w);
}

__device__ __forceinline__ float4 f4relu_add(float4 a, float4 b) {
    return make_float4(fmaxf(a.x + b.x, 0.f), fmaxf(a.y + b.y, 0.f),
                       fmaxf(a.z + b.z, 0.f), fmaxf(a.w + b.w, 0.f));
}

__device__ __forceinline__ uint2 f4_to_h4(float4 v) {
    __half2 lo = __floats2half2_rn(v.x, v.y);
    __half2 hi = __floats2half2_rn(v.z, v.w);
    uint2 r;
    r.x = *reinterpret_cast<unsigned*>(&lo);
    r.y = *reinterpret_cast<unsigned*>(&hi);
    return r;
}

__device__ __forceinline__ float4 h4_to_f4(uint2 u) {
    __half2 lo = *reinterpret_cast<__half2*>(&u.x);
    __half2 hi = *reinterpret_cast<__half2*>(&u.y);
    float2 a = __half22float2(lo);
    float2 b = __half22float2(hi);
    return make_float4(a.x, a.y, b.x, b.y);
}

// fp16 tensor-core mma: D(f32) += A(f16,row) * B(f16,col), m16n8k16
__device__ __forceinline__ void mma_f16(float c[4], unsigned a0, unsigned a1,
                                        unsigned a2, unsigned a3,
                                        unsigned b0, unsigned b1) {
    asm volatile(
        "mma.sync.aligned.m16n8k16.row.col.f32.f16.f16.f32 "
        "{%0,%1,%2,%3}, {%4,%5,%6,%7}, {%8,%9}, {%0,%1,%2,%3};"
        : "+f"(c[0]), "+f"(c[1]), "+f"(c[2]), "+f"(c[3])
        : "r"(a0), "r"(a1), "r"(a2), "r"(a3), "r"(b0), "r"(b1));
}

// ---------------- counts: batch is sorted -> binary search per graph -------
__global__ void count_kernel(const int* __restrict__ batch) {
    int g = blockIdx.x * blockDim.x + threadIdx.x;
    if (g >= NG) return;
    int lo = 0, hi = NN;
    while (lo < hi) { int m = (lo + hi) >> 1; if (batch[m] < g) lo = m + 1; else hi = m; }
    int s = lo;
    lo = 0; hi = NN;
    while (lo < hi) { int m = (lo + hi) >> 1; if (batch[m] < g + 1) lo = m + 1; else hi = m; }
    d_gcnt[g] = fmaxf((float)(lo - s), 1.0f);
}

// ---------------- input linear: h = x @ W_in + b ; zeroes d_agg16; h16 -----
__global__ void __launch_bounds__(256) lin_in_kernel(const float* __restrict__ x,
                                                     const float* __restrict__ W,
                                                     const float* __restrict__ b) {
    __shared__ __align__(16) float4 Ws[INF_ * HV];
    __shared__ __align__(16) float4 bs[HV];
    int t = threadIdx.x;
    for (int j = t; j < INF_ * HV; j += 256) Ws[j] = ((const float4*)W)[j];
    if (t < HV) bs[t] = ((const float4*)b)[t];
    __syncthreads();

    int lane = t & 15, rloc = t >> 4;
    int row = blockIdx.x * 16 + rloc;

    ((uint2*)d_agg16)[row * HV + lane] = make_uint2(0u, 0u);

    if (row < NN) {
        float4 acc = bs[lane];
        const float* xr = x + row * INF_;
        #pragma unroll
        for (int k = 0; k < INF_; k++) {
            float xv = __ldg(xr + k);
            f4fma(acc, xv, Ws[k * HV + lane]);
        }
        ((float4*)d_h)[row * HV + lane] = acc;
        ((uint2*)d_h16)[row * HV + lane] = f4_to_h4(acc);
    }
}

// ---------------- edge kernel: agg16[dst] += relu(h16[src] + ea @ We + be) -
// fp16 vector REDs (8B/lane) halve the scatter traffic vs fp32 v4.
__global__ void __launch_bounds__(256) edge_kernel(const int* __restrict__ ei,
                                                   const float* __restrict__ eattr,
                                                   const float* __restrict__ eW,
                                                   const float* __restrict__ eb) {
    __shared__ __align__(16) float4 Ws[EDIM * HV];
    __shared__ __align__(16) float4 bs[HV];
    int t = threadIdx.x;
    if (t < EDIM * HV) Ws[t] = ((const float4*)eW)[t];
    if (t < HV) bs[t] = ((const float4*)eb)[t];
    __syncthreads();

    int e0   = blockIdx.x * EPB + (t >> 4) * 8;
    int lane = t & 15;

    int4 sa = __ldg((const int4*)(ei) + (e0 >> 2));
    int4 sb = __ldg((const int4*)(ei) + (e0 >> 2) + 1);
    int4 da = __ldg((const int4*)(ei + NE) + (e0 >> 2));
    int4 db = __ldg((const int4*)(ei + NE) + (e0 >> 2) + 1);
    int src[8] = {sa.x, sa.y, sa.z, sa.w, sb.x, sb.y, sb.z, sb.w};
    int dst[8] = {da.x, da.y, da.z, da.w, db.x, db.y, db.z, db.w};

    uint2 hr[8];
    #pragma unroll
    for (int j = 0; j < 8; j++)
        hr[j] = __ldg((const uint2*)d_h16 + src[j] * HV + lane);

    float4 a[8];
    #pragma unroll
    for (int j = 0; j < 8; j++) a[j] = __ldg((const float4*)eattr + e0 + j);

    float4 w0 = Ws[0 * HV + lane], w1 = Ws[1 * HV + lane];
    float4 w2 = Ws[2 * HV + lane], w3 = Ws[3 * HV + lane];
    float4 bv = bs[lane];

    #pragma unroll
    for (int j = 0; j < 8; j++) {
        float4 v = bv;
        f4fma(v, a[j].x, w0);
        f4fma(v, a[j].y, w1);
        f4fma(v, a[j].z, w2);
        f4fma(v, a[j].w, w3);
        float4 m = f4relu_add(v, h4_to_f4(hr[j]));
        red_addh4((uint2*)d_agg16 + dst[j] * HV + lane, f4_to_h4(m));
    }
}

// ---------------- fused node MLP via fp16 mma (f32 accumulate) -------------
__global__ void __launch_bounds__(256) mlp_fused_kernel(
    const float* __restrict__ W1, const float* __restrict__ b1,
    const float* __restrict__ g1, const float* __restrict__ be1,
    const float* __restrict__ rm1, const float* __restrict__ rv1,
    const float* __restrict__ W2, const float* __restrict__ b2,
    const float* __restrict__ g2, const float* __restrict__ be2,
    const float* __restrict__ rm2, const float* __restrict__ rv2,
    const float* __restrict__ epsp, const int* __restrict__ batch, int do_pn)
{
    __shared__ __align__(16) __half zs_h[64 * KP];
    __shared__ __align__(16) __half WT_h[64 * KP];
    __shared__ float bias1[H], bias2[H];

    int t = threadIdx.x;
    int lane = t & 31, w = t >> 5;
    int tig = lane & 3, g = lane >> 2;
    int m0 = (w & 3) * 16, n0 = (w >> 2) * 32;
    int R0 = blockIdx.x * 64;
    float epv = 1.0f + __ldg(epsp);

    if (t < H) {
        float s1 = __ldg(g1 + t) * rsqrtf(__ldg(rv1 + t) + BN_EPS);
        bias1[t] = fmaf(__ldg(b1 + t) - __ldg(rm1 + t), s1, __ldg(be1 + t));
        float s2 = __ldg(g2 + t) * rsqrtf(__ldg(rv2 + t) + BN_EPS);
        bias2[t] = fmaf(__ldg(b2 + t) - __ldg(rm2 + t), s2, __ldg(be2 + t));
    }

    // --- W1 staging: thread owns column n, k-range [16q,16q+16) ------------
    int n = t & 63, q = t >> 6;
    float s1n = __ldg(g1 + n) * rsqrtf(__ldg(rv1 + n) + BN_EPS);
    float wreg[16];
    #pragma unroll
    for (int j = 0; j < 16; j++)
        wreg[j] = __ldg(W1 + (q * 16 + j) * H + n);
    #pragma unroll
    for (int j = 0; j < 8; j++) {
        __half2 p = __floats2half2_rn(wreg[2 * j] * s1n, wreg[2 * j + 1] * s1n);
        *(__half2*)&WT_h[n * KP + q * 16 + 2 * j] = p;
    }

    // --- z staging: z = (1+eps)*h + agg16, rounded to half -----------------
    #pragma unroll
    for (int s = 0; s < 4; s++) {
        int idx = t + 256 * s;
        int k  = idx >> 4;
        int n4 = (idx & 15) * 4;
        float4 hv = __ldg((const float4*)d_h + R0 * HV + idx);
        float4 av = h4_to_f4(__ldg((const uint2*)d_agg16 + R0 * HV + idx));
        float4 z = make_float4(fmaf(epv, hv.x, av.x), fmaf(epv, hv.y, av.y),
                               fmaf(epv, hv.z, av.z), fmaf(epv, hv.w, av.w));
        *(uint2*)&zs_h[k * KP + n4] = f4_to_h4(z);
        if (do_pn) ((uint2*)d_agg16)[R0 * HV + idx] = make_uint2(0u, 0u);
    }
    __syncthreads();

    // --- GEMM1 --------------------------------------------------------------
    float c[4][4];
    #pragma unroll
    for (int nt = 0; nt < 4; nt++)
        c[nt][0] = c[nt][1] = c[nt][2] = c[nt][3] = 0.f;
    #pragma unroll
    for (int kk = 0; kk < 4; kk++) {
        int k0 = kk * 16;
        unsigned a0 = *(const unsigned*)&zs_h[(m0 + g) * KP + k0 + 2 * tig];
        unsigned a1 = *(const unsigned*)&zs_h[(m0 + g + 8) * KP + k0 + 2 * tig];
        unsigned a2 = *(const unsigned*)&zs_h[(m0 + g) * KP + k0 + 2 * tig + 8];
        unsigned a3 = *(const unsigned*)&zs_h[(m0 + g + 8) * KP + k0 + 2 * tig + 8];
        #pragma unroll
        for (int nt = 0; nt < 4; nt++) {
            const __half* bp = &WT_h[(n0 + nt * 8 + g) * KP + k0 + 2 * tig];
            unsigned b0 = *(const unsigned*)bp;
            unsigned b1 = *(const unsigned*)(bp + 8);
            mma_f16(c[nt], a0, a1, a2, a3, b0, b1);
        }
    }

    // --- W2 prefetch (overlaps barrier wait) -------------------------------
    float s2n = __ldg(g2 + n) * rsqrtf(__ldg(rv2 + n) + BN_EPS);
    #pragma unroll
    for (int j = 0; j < 16; j++)
        wreg[j] = __ldg(W2 + (q * 16 + j) * H + n);

    __syncthreads();

    // --- stage t = relu(c + bias1) -> zs_h ; scaled W2 -> WT_h -------------
    #pragma unroll
    for (int nt = 0; nt < 4; nt++) {
        int col = n0 + nt * 8 + 2 * tig;
        float bA0 = bias1[col], bA1 = bias1[col + 1];
        float v0 = fmaxf(c[nt][0] + bA0, 0.f), v1 = fmaxf(c[nt][1] + bA1, 0.f);
        float v2 = fmaxf(c[nt][2] + bA0, 0.f), v3 = fmaxf(c[nt][3] + bA1, 0.f);
        *(__half2*)&zs_h[(m0 + g) * KP + col]     = __floats2half2_rn(v0, v1);
        *(__half2*)&zs_h[(m0 + g + 8) * KP + col] = __floats2half2_rn(v2, v3);
    }
    #pragma unroll
    for (int j = 0; j < 8; j++) {
        __half2 p = __floats2half2_rn(wreg[2 * j] * s2n, wreg[2 * j + 1] * s2n);
        *(__half2*)&WT_h[n * KP + q * 16 + 2 * j] = p;
    }
    __syncthreads();

    // --- GEMM2 --------------------------------------------------------------
    #pragma unroll
    for (int nt = 0; nt < 4; nt++)
        c[nt][0] = c[nt][1] = c[nt][2] = c[nt][3] = 0.f;
    #pragma unroll
    for (int kk = 0; kk < 4; kk++) {
        int k0 = kk * 16;
        unsigned a0 = *(const unsigned*)&zs_h[(m0 + g) * KP + k0 + 2 * tig];
        unsigned a1 = *(const unsigned*)&zs_h[(m0 + g + 8) * KP + k0 + 2 * tig];
        unsigned a2 = *(const unsigned*)&zs_h[(m0 + g) * KP + k0 + 2 * tig + 8];
        unsigned a3 = *(const unsigned*)&zs_h[(m0 + g + 8) * KP + k0 + 2 * tig + 8];
        #pragma unroll
        for (int nt = 0; nt < 4; nt++) {
            const __half* bp = &WT_h[(n0 + nt * 8 + g) * KP + k0 + 2 * tig];
            unsigned b0 = *(const unsigned*)bp;
            unsigned b1 = *(const unsigned*)(bp + 8);
            mma_f16(c[nt], a0, a1, a2, a3, b0, b1);
        }
    }

    // --- epilogue: BN2+ReLU, store h, PN stats / pool ----------------------
    int rowA = R0 + m0 + g;
    int rowB = rowA + 8;
    bool okA = rowA < NN, okB = rowB < NN;
    int ggA = okA ? __ldg(batch + rowA) : 0;
    int ggB = okB ? __ldg(batch + rowB) : 0;
    float sqA = 0.f, sqB = 0.f;

    #pragma unroll
    for (int nt = 0; nt < 4; nt++) {
        int col = n0 + nt * 8 + 2 * tig;
        float bA0 = bias2[col], bA1 = bias2[col + 1];
        float v0 = fmaxf(c[nt][0] + bA0, 0.f), v1 = fmaxf(c[nt][1] + bA1, 0.f);
        float v2 = fmaxf(c[nt][2] + bA0, 0.f), v3 = fmaxf(c[nt][3] + bA1, 0.f);
        if (okA) *(float2*)&d_h[rowA * H + col] = make_float2(v0, v1);
        if (okB) *(float2*)&d_h[rowB * H + col] = make_float2(v2, v3);
        if (do_pn) {
            if (okA) red_add2((float2*)&d_gsum[ggA * H + col], v0, v1);
            if (okB) red_add2((float2*)&d_gsum[ggB * H + col], v2, v3);
            sqA = fmaf(v0, v0, fmaf(v1, v1, sqA));
            sqB = fmaf(v2, v2, fmaf(v3, v3, sqB));
        } else {
            if (okA) red_add2((float2*)&d_pool[ggA * H + col], v0, v1);
            if (okB) red_add2((float2*)&d_pool[ggB * H + col], v2, v3);
        }
    }
    if (do_pn) {
        sqA += __shfl_xor_sync(0xffffffffu, sqA, 1);
        sqA += __shfl_xor_sync(0xffffffffu, sqA, 2);
        sqB += __shfl_xor_sync(0xffffffffu, sqB, 1);
        sqB += __shfl_xor_sync(0xffffffffu, sqB, 2);
        if (tig == 0) {
            if (okA) atomicAdd(&d_gss[ggA], sqA);
            if (okB) atomicAdd(&d_gss[ggB], sqB);
        }
    }
}

// ---------------- PairNorm per-graph mean & inverse denom; self-re-zeros ---
__global__ void meaninv_kernel() {
    int g = blockIdx.x, c = threadIdx.x;     // 64 threads
    float cnt = d_gcnt[g];
    float s = d_gsum[g * H + c];
    d_gsum[g * H + c] = 0.f;
    float mean = s / cnt;
    d_mean[g * H + c] = mean;
    float part = mean * s;
    #pragma unroll
    for (int o = 16; o; o >>= 1) part += __shfl_down_sync(0xffffffffu, part, o);
    __shared__ float red[2];
    if ((c & 31) == 0) red[c >> 5] = part;
    __syncthreads();
    if (c == 0) {
        float ss = d_gss[g];
        d_gss[g] = 0.f;
        float var = (ss - (red[0] + red[1])) / cnt;
        d_invd[g] = rsqrtf(PN_EPS + var);
    }
}

// ---------------- PairNorm apply (also writes fp16 shadow) -----------------
__global__ void __launch_bounds__(256) norm_kernel(const int* __restrict__ batch) {
    int idx = blockIdx.x * 256 + threadIdx.x;    // exactly NN*HV
    int row = idx >> 4, ln = idx & 15;
    int g = __ldg(batch + row);
    float4 hv = ((const float4*)d_h)[idx];
    float4 m = ((const float4*)d_mean)[g * HV + ln];
    float id = d_invd[g];
    hv.x = (hv.x - m.x) * id;
    hv.y = (hv.y - m.y) * id;
    hv.z = (hv.z - m.z) * id;
    hv.w = (hv.w - m.w) * id;
    ((float4*)d_h)[idx] = hv;
    ((uint2*)d_h16)[idx] = f4_to_h4(hv);
}

// ---------------- classifier; self-re-zeros pool ---------------------------
__global__ void cls_kernel(const float* __restrict__ W, const float* __restrict__ b,
                           float* __restrict__ out) {
    int g = blockIdx.x, c = threadIdx.x;     // 64 threads
    float p = d_pool[g * H + c];
    d_pool[g * H + c] = 0.f;
    float a = p * W[c * NOUT + 0];
    float bb = p * W[c * NOUT + 1];
    #pragma unroll
    for (int o = 16; o; o >>= 1) {
        a  += __shfl_down_sync(0xffffffffu, a, o);
        bb += __shfl_down_sync(0xffffffffu, bb, o);
    }
    __shared__ float sa[2], sb[2];
    if ((c & 31) == 0) { sa[c >> 5] = a; sb[c >> 5] = bb; }
    __syncthreads();
    if (c == 0) {
        out[g * NOUT + 0] = sa[0] + sa[1] + b[0];
        out[g * NOUT + 1] = sb[0] + sb[1] + b[1];
    }
}

// ---------------------------------------------------------------------------
extern "C" void kernel_launch(void* const* d_in, const int* in_sizes, int n_in,
                              void* d_out, int out_size) {
    const float* x        = (const float*)d_in[0];
    const int*   ei       = (const int*)  d_in[1];
    const float* eattr    = (const float*)d_in[2];
    const int*   batch    = (const int*)  d_in[3];
    const float* lin_W    = (const float*)d_in[4];
    const float* lin_b    = (const float*)d_in[5];
    const float* edge_W   = (const float*)d_in[6];
    const float* edge_b   = (const float*)d_in[7];
    const float* mlp_W1   = (const float*)d_in[8];
    const float* mlp_b1   = (const float*)d_in[9];
    const float* mbn_g    = (const float*)d_in[10];
    const float* mbn_b    = (const float*)d_in[11];
    const float* mbn_rm   = (const float*)d_in[12];
    const float* mbn_rv   = (const float*)d_in[13];
    const float* mlp_W2   = (const float*)d_in[14];
    const float* mlp_b2   = (const float*)d_in[15];
    const float* eps      = (const float*)d_in[16];
    const float* bn_g     = (const float*)d_in[17];
    const float* bn_b     = (const float*)d_in[18];
    const float* bn_rm    = (const float*)d_in[19];
    const float* bn_rv    = (const float*)d_in[20];
    const float* cls_W    = (const float*)d_in[21];
    const float* cls_b    = (const float*)d_in[22];
    float* out = (float*)d_out;

    count_kernel<<<2, 256>>>(batch);
    lin_in_kernel<<<NPAD / 16, 256>>>(x, lin_W, lin_b);

    for (int i = 0; i < NL; i++) {
        edge_kernel<<<NE / EPB, 256>>>(ei, eattr, edge_W + i * EDIM * H, edge_b + i * H);
        int do_pn = (i < NL - 1) ? 1 : 0;
        mlp_fused_kernel<<<NPAD / 64, 256>>>(
            mlp_W1 + i * H * H, mlp_b1 + i * H,
            mbn_g + i * H, mbn_b + i * H, mbn_rm + i * H, mbn_rv + i * H,
            mlp_W2 + i * H * H, mlp_b2 + i * H,
            bn_g + i * H, bn_b + i * H, bn_rm + i * H, bn_rv + i * H,
            eps + i, batch, do_pn);
        if (do_pn) {
            meaninv_kernel<<<NG, H>>>();
            norm_kernel<<<(NN * HV) / 256, 256>>>(batch);
        }
    }

    cls_kernel<<<NG, H>>>(cls_W, cls_b, out);
}